// round 11
// baseline (speedup 1.0000x reference)
#include <cuda_runtime.h>
#include <cstdint>

#define S_LEN  2048
#define HKV    2
#define HQ     16
#define GQA    8
#define DIM    64
#define LC     32
#define CSTRIDE 16
#define LB     64
#define KSEL   8
#define WIN    512
#define SC_N   127
#define NOUT   31
#define SCALE  0.125f
#define QT     8
#define NT     256
#define RS     76            // padded row stride (floats): conflict-free LDS.128
#define RS2    19            // RS in ulonglong2
#define RSU    38            // RS in u64

typedef unsigned long long u64t;

__device__ float g_ck[HKV * SC_N * DIM];
__device__ float g_cv[HKV * SC_N * DIM];

__device__ __forceinline__ float dot4(float4 a, float4 b) {
    return a.x * b.x + a.y * b.y + a.z * b.z + a.w * b.w;
}
__device__ __forceinline__ void ffma2(u64t& d, u64t a, u64t b) {
    asm("fma.rn.f32x2 %0, %1, %2, %0;" : "+l"(d) : "l"(a), "l"(b));
}
__device__ __forceinline__ void mul2(u64t& d, u64t a, u64t b) {
    asm("mul.rn.f32x2 %0, %1, %2;" : "=l"(d) : "l"(a), "l"(b));
}
__device__ __forceinline__ void add2(u64t& d, u64t a, u64t b) {
    asm("add.rn.f32x2 %0, %1, %2;" : "=l"(d) : "l"(a), "l"(b));
}
__device__ __forceinline__ u64t pack2(float lo, float hi) {
    u64t r; asm("mov.b64 %0, {%1, %2};" : "=l"(r) : "f"(lo), "f"(hi)); return r;
}
__device__ __forceinline__ float2 unpack2(u64t a) {
    float2 r; asm("mov.b64 {%0, %1}, %2;" : "=f"(r.x), "=f"(r.y) : "l"(a)); return r;
}
__device__ __forceinline__ void cp16(void* sdst, const void* gsrc) {
    uint32_t sa = (uint32_t)__cvta_generic_to_shared(sdst);
    asm volatile("cp.async.cg.shared.global [%0], [%1], 16;" :: "r"(sa), "l"(gsrc));
}
#define CP_COMMIT() asm volatile("cp.async.commit_group;")
#define CP_WAIT0()  asm volatile("cp.async.wait_group 0;")

extern __shared__ float pool3[];

// ---------------------------------------------------------------------------
// conv1d compressor: block = (hkv, k/v, o-quarter, 8 compressed positions)
// ---------------------------------------------------------------------------
__global__ void __launch_bounds__(256) compress_kernel(
    const float* __restrict__ k, const float* __restrict__ v,
    const float* __restrict__ wk, const float* __restrict__ wv)
{
    const int b     = blockIdx.x;        // 256 blocks
    const int hkv   = b & 1;
    const int isV   = (b >> 1) & 1;
    const int oq    = (b >> 2) & 3;
    const int c0    = (b >> 4) * 8;
    const float* src = isV ? v : k;
    const float* w   = isV ? wv : wk;
    float* dst = isV ? g_cv : g_ck;

    __shared__ float xs[144 * 64];
    __shared__ float red[16 * 8 * 16];
    const int tid = threadIdx.x;

    for (int idx = tid; idx < 144 * 16; idx += NT) {
        int row = idx >> 4, quad = idx & 15;
        int pos = c0 * CSTRIDE + row;
        float4 val = make_float4(0.f, 0.f, 0.f, 0.f);
        if (pos < S_LEN)
            val = __ldg((const float4*)(src + (pos * HKV + hkv) * DIM) + quad);
        ((float4*)(xs + row * 64))[quad] = val;
    }
    __syncthreads();

    const int ol   = tid & 15;
    const int o    = oq * 16 + ol;
    const int part = tid >> 4;
    float acc[8];
    #pragma unroll
    for (int cc = 0; cc < 8; ++cc) acc[cc] = 0.f;

    for (int i = part * 4; i < part * 4 + 4; ++i) {
        const float4* w4 = (const float4*)(w + (o * DIM + i) * LC);
        #pragma unroll
        for (int t4 = 0; t4 < 8; ++t4) {
            float4 a = __ldg(&w4[t4]);
            int t = t4 * 4;
            #pragma unroll
            for (int cc = 0; cc < 8; ++cc) {
                const float* xr = xs + (cc * 16 + t) * 64 + i;
                acc[cc] += a.x * xr[0] + a.y * xr[64] + a.z * xr[128] + a.w * xr[192];
            }
        }
    }
    #pragma unroll
    for (int cc = 0; cc < 8; ++cc) red[(part * 8 + cc) * 16 + ol] = acc[cc];
    __syncthreads();
    if (part == 0) {
        #pragma unroll
        for (int cc = 0; cc < 8; ++cc) {
            if (c0 + cc < SC_N) {
                float a = 0.f;
                #pragma unroll
                for (int p = 0; p < 16; ++p) a += red[(p * 8 + cc) * 16 + ol];
                dst[(hkv * SC_N + c0 + cc) * DIM + o] = a;
            }
        }
    }
}

// ---------------------------------------------------------------------------
// Merged NSA kernel (2 CTAs/SM target).
// ---------------------------------------------------------------------------
__global__ void __launch_bounds__(256, 2) nsa_main(
    const float* __restrict__ q, const float* __restrict__ k,
    const float* __restrict__ v, const float* __restrict__ wg,
    float* __restrict__ out)
{
    __shared__ unsigned selmaskSh[QT];
    __shared__ int blkList[32];
    __shared__ int nblkSh;

    float* ckT = pool3;
    float* cvT = pool3 + 9728;
    float* qs  = pool3 + 19456;
    float* pkv = pool3 + 23808;

    const int bxr  = gridDim.x - 1 - blockIdx.x;   // heavy-first
    const int hkv  = bxr & 1;
    const int s0   = (bxr >> 1) * QT;
    const int tid  = threadIdx.x;
    const int lane = tid & 31;
    const int warp = tid >> 5;
    const int s    = s0 + warp;

    // ---- stage ck/cv tiles ----
    {
        const float* ckb = g_ck + hkv * SC_N * DIM;
        const float* cvb = g_cv + hkv * SC_N * DIM;
        for (int idx = tid; idx < 128 * 16; idx += NT) {
            int row = idx >> 4, quad = idx & 15;
            int c = row < SC_N ? row : SC_N - 1;
            cp16(ckT + row * RS + quad * 4, ckb + c * DIM + quad * 4);
            cp16(cvT + row * RS + quad * 4, cvb + c * DIM + quad * 4);
        }
        CP_COMMIT();
    }

    // ---- q fragments, gates, stage q ----
    float gate0, gate1, gate2;
    {
        const int h   = lane >> 2;
        const int d16 = lane & 3;
        const float4* qrow = (const float4*)(q + (s * HQ + hkv * GQA + h) * DIM);
        float4 qf[4];
        #pragma unroll
        for (int r = 0; r < 4; ++r) qf[r] = __ldg(&qrow[d16 * 4 + r]);
        #pragma unroll
        for (int e = 0; e < 3; ++e) {
            const float4* wrow = (const float4*)(wg + e * DIM);
            float a = 0.f;
            #pragma unroll
            for (int r = 0; r < 4; ++r) a += dot4(qf[r], __ldg(&wrow[d16 * 4 + r]));
            a += __shfl_xor_sync(~0u, a, 1);
            a += __shfl_xor_sync(~0u, a, 2);
            if (e == 0) gate0 = a; else if (e == 1) gate1 = a; else gate2 = a;
        }
        float4* qdst = (float4*)(qs + warp * 544 + h * 68);
        #pragma unroll
        for (int r = 0; r < 4; ++r) qdst[d16 * 4 + r] = qf[r];
    }

    const int Nc = (s >= 31) ? (((s - 31) >> 4) + 1) : 0;
    const ulonglong2* qq2 = (const ulonglong2*)(qs + warp * 544);

    CP_WAIT0();
    __syncthreads();

    // ======================= PHASE 1: compressed branch =====================
    float scA[4][8];
    #pragma unroll
    for (int t = 0; t < 2; ++t) {
        u64t s1[8], s2[8];
        #pragma unroll
        for (int hh = 0; hh < 8; ++hh) { s1[hh] = 0ull; s2[hh] = 0ull; }
        const ulonglong2* kA = (const ulonglong2*)ckT + (t * 64 + lane) * RS2;
        const ulonglong2* kB = kA + 32 * RS2;
        #pragma unroll
        for (int d4 = 0; d4 < 16; ++d4) {
            ulonglong2 a = kA[d4];
            ulonglong2 bb = kB[d4];
            #pragma unroll
            for (int hh = 0; hh < 8; ++hh) {
                ulonglong2 qv = qq2[hh * 17 + d4];
                ffma2(s1[hh], qv.x, a.x);
                ffma2(s1[hh], qv.y, a.y);
                ffma2(s2[hh], qv.x, bb.x);
                ffma2(s2[hh], qv.y, bb.y);
            }
        }
        #pragma unroll
        for (int hh = 0; hh < 8; ++hh) {
            float2 f1 = unpack2(s1[hh]);
            float2 f2 = unpack2(s2[hh]);
            scA[2 * t][hh]     = (f1.x + f1.y) * SCALE;
            scA[2 * t + 1][hh] = (f2.x + f2.y) * SCALE;
        }
    }
    __syncthreads();    // ckT consumed; probs may overlay it

    {
        float* probsW = pool3 + warp * 1024;   // [128][8] overlay on ckT
        float* pkvW   = pkv + warp * 128;

        bool valid[4];
        #pragma unroll
        for (int ki = 0; ki < 4; ++ki) valid[ki] = (ki * 32 + lane) < Nc;

        // per-head exact max, then exp IN PLACE over scA
        #pragma unroll
        for (int hh = 0; hh < 8; ++hh) {
            float lm = -1e30f;
            #pragma unroll
            for (int ki = 0; ki < 4; ++ki)
                if (valid[ki]) lm = fmaxf(lm, scA[ki][hh]);
            #pragma unroll
            for (int off = 16; off; off >>= 1)
                lm = fmaxf(lm, __shfl_xor_sync(~0u, lm, off));
            #pragma unroll
            for (int ki = 0; ki < 4; ++ki)
                scA[ki][hh] = valid[ki] ? expf(scA[ki][hh] - lm) : 0.f;
        }

        float inv[8];
        #pragma unroll
        for (int hp = 0; hp < 4; ++hp) {
            float sa = scA[0][2*hp]   + scA[1][2*hp]   + scA[2][2*hp]   + scA[3][2*hp];
            float sb = scA[0][2*hp+1] + scA[1][2*hp+1] + scA[2][2*hp+1] + scA[3][2*hp+1];
            u64t p = pack2(sa, sb);
            #pragma unroll
            for (int off = 16; off; off >>= 1) {
                u64t o = __shfl_xor_sync(~0u, p, off);
                add2(p, p, o);
            }
            float2 f = unpack2(p);
            inv[2*hp]   = (f.x > 0.f) ? (1.f / f.x) : 0.f;
            inv[2*hp+1] = (f.y > 0.f) ? (1.f / f.y) : 0.f;
        }

        #pragma unroll
        for (int ki = 0; ki < 4; ++ki) {
            int c = ki * 32 + lane;
            float p0 = scA[ki][0]*inv[0], p1 = scA[ki][1]*inv[1];
            float p2 = scA[ki][2]*inv[2], p3 = scA[ki][3]*inv[3];
            float p4 = scA[ki][4]*inv[4], p5 = scA[ki][5]*inv[5];
            float p6 = scA[ki][6]*inv[6], p7 = scA[ki][7]*inv[7];
            float4* pw = (float4*)(probsW + c * 8);
            pw[0] = make_float4(p0, p1, p2, p3);
            pw[1] = make_float4(p4, p5, p6, p7);
            pkvW[c] = p0 + p1 + p2 + p3 + p4 + p5 + p6 + p7;
        }
        __syncwarp();

        // pooling + top-8
        {
            float myval;
            if (lane < NOUT) {
                const float* pv = pkvW + lane * 4;
                myval = (pv[0] + pv[1] + pv[2] + pv[3] + pv[4]) / 5.0f;
            } else {
                myval = -1.0f;
            }
            if (lane == (s >> 6)) myval = __int_as_float(0x7f800000);
            unsigned mask = 0;
            #pragma unroll
            for (int r = 0; r < KSEL; ++r) {
                float bv = myval; int bi = lane;
                #pragma unroll
                for (int off = 16; off; off >>= 1) {
                    float ov = __shfl_xor_sync(~0u, bv, off);
                    int   oi = __shfl_xor_sync(~0u, bi, off);
                    if (ov > bv || (ov == bv && oi < bi)) { bv = ov; bi = oi; }
                }
                mask |= 1u << bi;
                if (lane == bi) myval = __int_as_float(0xff800000);
            }
            if (lane == 0) selmaskSh[warp] = mask;
        }

        // cmp PV -> out = g2 * cmp
        u64t acc2[8];
        #pragma unroll
        for (int i = 0; i < 8; ++i) acc2[i] = 0ull;
        const u64t* vB = (const u64t*)cvT + lane;
        const float4* pB = (const float4*)probsW;
        #pragma unroll 2
        for (int c = 0; c < Nc; ++c) {
            u64t vj = vB[c * RSU];
            float4 pa = pB[c * 2], pb = pB[c * 2 + 1];
            ffma2(acc2[0], pack2(pa.x, pa.x), vj);
            ffma2(acc2[1], pack2(pa.y, pa.y), vj);
            ffma2(acc2[2], pack2(pa.z, pa.z), vj);
            ffma2(acc2[3], pack2(pa.w, pa.w), vj);
            ffma2(acc2[4], pack2(pb.x, pb.x), vj);
            ffma2(acc2[5], pack2(pb.y, pb.y), vj);
            ffma2(acc2[6], pack2(pb.z, pb.z), vj);
            ffma2(acc2[7], pack2(pb.w, pb.w), vj);
        }
        #pragma unroll
        for (int hh = 0; hh < 8; ++hh) {
            float g2h = __shfl_sync(~0u, gate2, hh * 4);
            float2 a = unpack2(acc2[hh]);
            float2* op = (float2*)(out + (s * HQ + hkv * GQA + hh) * DIM + 2 * lane);
            *op = make_float2(g2h * a.x, g2h * a.y);
        }
    }

    // ======================= PHASE 2: sel + swa ==============================
    __syncthreads();
    if (tid == 0) {
        unsigned cmb = 0;
        #pragma unroll
        for (int qq = 0; qq < QT; ++qq) cmb |= selmaskSh[qq];
        int loS = s0 - (WIN - 1); if (loS < 0) loS = 0;
        int lowBlk = loS >> 6;
        int hiBlk  = (s0 + QT - 1) >> 6;
        unsigned wmask = (hiBlk >= 31 ? 0xFFFFFFFFu : ((1u << (hiBlk + 1)) - 1u))
                       & ~((1u << lowBlk) - 1u);
        unsigned m = cmb | wmask;
        int n = 0;
        while (m) { int bb = __ffs(m) - 1; m &= m - 1; blkList[n++] = bb; }
        nblkSh = n;
    }
    __syncthreads();

    const unsigned selMine = selmaskSh[warp];
    const int nblk = nblkSh;

    u64t accS2[8], accW2[8], lsw2[8];
    #pragma unroll
    for (int i = 0; i < 8; ++i) { accS2[i] = 0ull; accW2[i] = 0ull; lsw2[i] = 0ull; }
    float mU = -1e30f;
    const int winLo = s - (WIN - 1);
    float* probsW2 = pool3 + 23808 + warp * 512;

    {
        int base = blkList[0] * LB;
        float* Kd = pool3;
        float* Vd = pool3 + 4864;
        #pragma unroll
        for (int r = 0; r < 4; ++r) {
            int idx = tid + r * NT;
            int row = idx >> 4, quad = idx & 15;
            int pos = base + row;
            cp16(Kd + row * RS + quad * 4, (const float4*)(k + (pos * HKV + hkv) * DIM) + quad);
            cp16(Vd + row * RS + quad * 4, (const float4*)(v + (pos * HKV + hkv) * DIM) + quad);
        }
        CP_COMMIT();
    }

    for (int it = 0; it < nblk; ++it) {
        CP_WAIT0();
        __syncthreads();
        if (it + 1 < nblk) {
            int base = blkList[it + 1] * LB;
            float* Kd = pool3 + ((it + 1) & 1) * 9728;
            float* Vd = Kd + 4864;
            #pragma unroll
            for (int r = 0; r < 4; ++r) {
                int idx = tid + r * NT;
                int row = idx >> 4, quad = idx & 15;
                int pos = base + row;
                cp16(Kd + row * RS + quad * 4, (const float4*)(k + (pos * HKV + hkv) * DIM) + quad);
                cp16(Vd + row * RS + quad * 4, (const float4*)(v + (pos * HKV + hkv) * DIM) + quad);
            }
            CP_COMMIT();
        }
        const float* Kt = pool3 + (it & 1) * 9728;
        const float* Vt = Kt + 4864;
        const int b = blkList[it];
        const int base = b * LB;

        if (base > s) continue;
        const bool selAct = (selMine >> b) & 1u;
        const bool swaAct = (base + 63) >= winLo;
        if (!(selAct || swaAct)) continue;

        // ---- score pass ----
        u64t s1[8], s2[8];
        #pragma unroll
        for (int hh = 0; hh < 8; ++hh) { s1[hh] = 0ull; s2[hh] = 0ull; }
        {
            const ulonglong2* kA = (const ulonglong2*)Kt + lane * RS2;
            const ulonglong2* kB = kA + 32 * RS2;
            #pragma unroll
            for (int d4 = 0; d4 < 16; ++d4) {
                ulonglong2 a = kA[d4];
                ulonglong2 bb = kB[d4];
                #pragma unroll
                for (int hh = 0; hh < 8; ++hh) {
                    ulonglong2 qv = qq2[hh * 17 + d4];
                    ffma2(s1[hh], qv.x, a.x);
                    ffma2(s1[hh], qv.y, a.y);
                    ffma2(s2[hh], qv.x, bb.x);
                    ffma2(s2[hh], qv.y, bb.y);
                }
            }
        }

        const int jhi  = min(63, s - base);
        const int pos1 = base + lane;
        const bool c1 = (lane <= jhi);
        const bool c2 = (lane + 32 <= jhi);
        const bool w1 = c1 && (pos1 >= winLo);
        const bool w2 = c2 && (pos1 + 32 >= winLo);

        float sc1[8], sc2[8];
        float tS = -1e30f, tW = -1e30f;
        #pragma unroll
        for (int hh = 0; hh < 8; ++hh) {
            float2 f1 = unpack2(s1[hh]);
            float2 f2 = unpack2(s2[hh]);
            sc1[hh] = (f1.x + f1.y) * SCALE;
            sc2[hh] = (f2.x + f2.y) * SCALE;
            if (c1) { tS = fmaxf(tS, sc1[hh]); if (w1) tW = fmaxf(tW, sc1[hh]); }
            if (c2) { tS = fmaxf(tS, sc2[hh]); if (w2) tW = fmaxf(tW, sc2[hh]); }
        }
        #pragma unroll
        for (int off = 16; off; off >>= 1) {
            tS = fmaxf(tS, __shfl_xor_sync(~0u, tS, off));
            tW = fmaxf(tW, __shfl_xor_sync(~0u, tW, off));
        }

        const bool doS = selAct;
        const bool doW = swaAct && (tW > -1e29f);
        float t = -1e30f;
        if (doS) t = tS;
        if (doW) t = fmaxf(t, tW);
        if (t > mU) {
            float f = __expf(mU - t);
            u64t f2p = pack2(f, f);
            #pragma unroll
            for (int i = 0; i < 8; ++i) {
                mul2(accS2[i], accS2[i], f2p);
                mul2(accW2[i], accW2[i], f2p);
                mul2(lsw2[i], lsw2[i], f2p);
            }
            mU = t;
        }

        // exps IN PLACE over sc1/sc2
        #pragma unroll
        for (int hh = 0; hh < 8; ++hh) {
            sc1[hh] = __expf(sc1[hh] - mU);
            sc2[hh] = __expf(sc2[hh] - mU);
        }
        {
            float4* pw = (float4*)probsW2;
            if (c1) {
                pw[lane * 2]     = make_float4(sc1[0], sc1[1], sc1[2], sc1[3]);
                pw[lane * 2 + 1] = make_float4(sc1[4], sc1[5], sc1[6], sc1[7]);
            }
            if (c2) {
                pw[(lane + 32) * 2]     = make_float4(sc2[0], sc2[1], sc2[2], sc2[3]);
                pw[(lane + 32) * 2 + 1] = make_float4(sc2[4], sc2[5], sc2[6], sc2[7]);
            }
        }
        u64t sum2[8];
        #pragma unroll
        for (int hh = 0; hh < 8; ++hh) {
            float sS = (doS && c1 ? sc1[hh] : 0.f) + (doS && c2 ? sc2[hh] : 0.f);
            float sW = (w1 ? sc1[hh] : 0.f) + (w2 ? sc2[hh] : 0.f);
            sum2[hh] = pack2(sS, sW);
        }
        #pragma unroll
        for (int off = 16; off; off >>= 1) {
            #pragma unroll
            for (int hh = 0; hh < 8; ++hh) {
                u64t o = __shfl_xor_sync(~0u, sum2[hh], off);
                add2(sum2[hh], sum2[hh], o);
            }
        }
        #pragma unroll
        for (int hh = 0; hh < 8; ++hh) add2(lsw2[hh], lsw2[hh], sum2[hh]);
        __syncwarp();

        // ---- PV pass ----
        const u64t* vB = (const u64t*)Vt + lane;
        const float4* pB = (const float4*)probsW2;
        const int jlo = max(0, winLo - base);

        if (doS && doW) {
            for (int j = 0; j < jlo; ++j) {
                u64t vj = vB[j * RSU];
                float4 pa = pB[j * 2], pb = pB[j * 2 + 1];
                ffma2(accS2[0], pack2(pa.x, pa.x), vj);
                ffma2(accS2[1], pack2(pa.y, pa.y), vj);
                ffma2(accS2[2], pack2(pa.z, pa.z), vj);
                ffma2(accS2[3], pack2(pa.w, pa.w), vj);
                ffma2(accS2[4], pack2(pb.x, pb.x), vj);
                ffma2(accS2[5], pack2(pb.y, pb.y), vj);
                ffma2(accS2[6], pack2(pb.z, pb.z), vj);
                ffma2(accS2[7], pack2(pb.w, pb.w), vj);
            }
            u64t accT2[8];
            #pragma unroll
            for (int i = 0; i < 8; ++i) accT2[i] = 0ull;
            for (int j = jlo; j <= jhi; ++j) {
                u64t vj = vB[j * RSU];
                float4 pa = pB[j * 2], pb = pB[j * 2 + 1];
                ffma2(accT2[0], pack2(pa.x, pa.x), vj);
                ffma2(accT2[1], pack2(pa.y, pa.y), vj);
                ffma2(accT2[2], pack2(pa.z, pa.z), vj);
                ffma2(accT2[3], pack2(pa.w, pa.w), vj);
                ffma2(accT2[4], pack2(pb.x, pb.x), vj);
                ffma2(accT2[5], pack2(pb.y, pb.y), vj);
                ffma2(accT2[6], pack2(pb.z, pb.z), vj);
                ffma2(accT2[7], pack2(pb.w, pb.w), vj);
            }
            #pragma unroll
            for (int i = 0; i < 8; ++i) {
                add2(accS2[i], accS2[i], accT2[i]);
                add2(accW2[i], accW2[i], accT2[i]);
            }
        } else if (doS) {
            for (int j = 0; j <= jhi; ++j) {
                u64t vj = vB[j * RSU];
                float4 pa = pB[j * 2], pb = pB[j * 2 + 1];
                ffma2(accS2[0], pack2(pa.x, pa.x), vj);
                ffma2(accS2[1], pack2(pa.y, pa.y), vj);
                ffma2(accS2[2], pack2(pa.z, pa.z), vj);
                ffma2(accS2[3], pack2(pa.w, pa.w), vj);
                ffma2(accS2[4], pack2(pb.x, pb.x), vj);
                ffma2(accS2[5], pack2(pb.y, pb.y), vj);
                ffma2(accS2[6], pack2(pb.z, pb.z), vj);
                ffma2(accS2[7], pack2(pb.w, pb.w), vj);
            }
        } else if (doW) {
            for (int j = jlo; j <= jhi; ++j) {
                u64t vj = vB[j * RSU];
                float4 pa = pB[j * 2], pb = pB[j * 2 + 1];
                ffma2(accW2[0], pack2(pa.x, pa.x), vj);
                ffma2(accW2[1], pack2(pa.y, pa.y), vj);
                ffma2(accW2[2], pack2(pa.z, pa.z), vj);
                ffma2(accW2[3], pack2(pa.w, pa.w), vj);
                ffma2(accW2[4], pack2(pb.x, pb.x), vj);
                ffma2(accW2[5], pack2(pb.y, pb.y), vj);
                ffma2(accW2[6], pack2(pb.z, pb.z), vj);
                ffma2(accW2[7], pack2(pb.w, pb.w), vj);
            }
        }
    }

    // ---- combine per head, RMW of phase-1 result ----
    #pragma unroll
    for (int hh = 0; hh < 8; ++hh) {
        float g0 = __shfl_sync(~0u, gate0, hh * 4);
        float g1 = __shfl_sync(~0u, gate1, hh * 4);
        float2 lw = unpack2(lsw2[hh]);
        float invS = g0 / fmaxf(lw.x, 1e-20f);
        float invW = g1 / fmaxf(lw.y, 1e-20f);
        float2 aS = unpack2(accS2[hh]);
        float2 aW = unpack2(accW2[hh]);
        float2* op = (float2*)(out + (s * HQ + hkv * GQA + hh) * DIM + 2 * lane);
        float2 cur = *op;
        cur.x += invS * aS.x + invW * aW.x;
        cur.y += invS * aS.y + invW * aW.y;
        *op = cur;
    }
}

// ---------------------------------------------------------------------------
extern "C" void kernel_launch(void* const* d_in, const int* in_sizes, int n_in,
                              void* d_out, int out_size)
{
    const float* q  = (const float*)d_in[0];
    const float* k  = (const float*)d_in[1];
    const float* v  = (const float*)d_in[2];
    const float* wk = (const float*)d_in[3];
    const float* wv = (const float*)d_in[4];
    const float* wg = (const float*)d_in[5];
    float* out = (float*)d_out;

    compress_kernel<<<256, NT>>>(k, v, wk, wv);

    const size_t smem_bytes = 27904 * sizeof(float);   // 111616 B
    cudaFuncSetAttribute(nsa_main,
                         cudaFuncAttributeMaxDynamicSharedMemorySize, (int)smem_bytes);
    nsa_main<<<(S_LEN / QT) * HKV, NT, smem_bytes>>>(q, k, v, wg, out);
}

// round 12
// speedup vs baseline: 1.0409x; 1.0409x over previous
#include <cuda_runtime.h>
#include <cstdint>

#define S_LEN  2048
#define HKV    2
#define HQ     16
#define GQA    8
#define DIM    64
#define LC     32
#define CSTRIDE 16
#define LB     64
#define KSEL   8
#define WIN    512
#define SC_N   127
#define NOUT   31
#define SCALE  0.125f
#define QT     8
#define NT     256
#define RS     76            // padded row stride (floats): conflict-free LDS.128
#define RS2    19            // RS in ulonglong2
#define RSU    38            // RS in u64

typedef unsigned long long u64t;

__device__ float g_ck[HKV * SC_N * DIM];
__device__ float g_cv[HKV * SC_N * DIM];

__device__ __forceinline__ float dot4(float4 a, float4 b) {
    return a.x * b.x + a.y * b.y + a.z * b.z + a.w * b.w;
}
__device__ __forceinline__ void ffma2(u64t& d, u64t a, u64t b) {
    asm("fma.rn.f32x2 %0, %1, %2, %0;" : "+l"(d) : "l"(a), "l"(b));
}
__device__ __forceinline__ void mul2(u64t& d, u64t a, u64t b) {
    asm("mul.rn.f32x2 %0, %1, %2;" : "=l"(d) : "l"(a), "l"(b));
}
__device__ __forceinline__ void add2(u64t& d, u64t a, u64t b) {
    asm("add.rn.f32x2 %0, %1, %2;" : "=l"(d) : "l"(a), "l"(b));
}
__device__ __forceinline__ u64t pack2(float lo, float hi) {
    u64t r; asm("mov.b64 %0, {%1, %2};" : "=l"(r) : "f"(lo), "f"(hi)); return r;
}
__device__ __forceinline__ float2 unpack2(u64t a) {
    float2 r; asm("mov.b64 {%0, %1}, %2;" : "=f"(r.x), "=f"(r.y) : "l"(a)); return r;
}
__device__ __forceinline__ void cp16(void* sdst, const void* gsrc) {
    uint32_t sa = (uint32_t)__cvta_generic_to_shared(sdst);
    asm volatile("cp.async.cg.shared.global [%0], [%1], 16;" :: "r"(sa), "l"(gsrc));
}
#define CP_COMMIT() asm volatile("cp.async.commit_group;")
#define CP_WAIT0()  asm volatile("cp.async.wait_group 0;")

extern __shared__ float pool3[];

// ---------------------------------------------------------------------------
// conv1d compressor: block = (hkv, k/v, o-quarter, 8 compressed positions)
// ---------------------------------------------------------------------------
__global__ void __launch_bounds__(256) compress_kernel(
    const float* __restrict__ k, const float* __restrict__ v,
    const float* __restrict__ wk, const float* __restrict__ wv)
{
    const int b     = blockIdx.x;        // 256 blocks
    const int hkv   = b & 1;
    const int isV   = (b >> 1) & 1;
    const int oq    = (b >> 2) & 3;
    const int c0    = (b >> 4) * 8;
    const float* src = isV ? v : k;
    const float* w   = isV ? wv : wk;
    float* dst = isV ? g_cv : g_ck;

    __shared__ float xs[144 * 64];
    __shared__ float red[16 * 8 * 16];
    const int tid = threadIdx.x;

    for (int idx = tid; idx < 144 * 16; idx += NT) {
        int row = idx >> 4, quad = idx & 15;
        int pos = c0 * CSTRIDE + row;
        float4 val = make_float4(0.f, 0.f, 0.f, 0.f);
        if (pos < S_LEN)
            val = __ldg((const float4*)(src + (pos * HKV + hkv) * DIM) + quad);
        ((float4*)(xs + row * 64))[quad] = val;
    }
    __syncthreads();

    const int ol   = tid & 15;
    const int o    = oq * 16 + ol;
    const int part = tid >> 4;
    float acc[8];
    #pragma unroll
    for (int cc = 0; cc < 8; ++cc) acc[cc] = 0.f;

    for (int i = part * 4; i < part * 4 + 4; ++i) {
        const float4* w4 = (const float4*)(w + (o * DIM + i) * LC);
        #pragma unroll
        for (int t4 = 0; t4 < 8; ++t4) {
            float4 a = __ldg(&w4[t4]);
            int t = t4 * 4;
            #pragma unroll
            for (int cc = 0; cc < 8; ++cc) {
                const float* xr = xs + (cc * 16 + t) * 64 + i;
                acc[cc] += a.x * xr[0] + a.y * xr[64] + a.z * xr[128] + a.w * xr[192];
            }
        }
    }
    #pragma unroll
    for (int cc = 0; cc < 8; ++cc) red[(part * 8 + cc) * 16 + ol] = acc[cc];
    __syncthreads();
    if (part == 0) {
        #pragma unroll
        for (int cc = 0; cc < 8; ++cc) {
            if (c0 + cc < SC_N) {
                float a = 0.f;
                #pragma unroll
                for (int p = 0; p < 16; ++p) a += red[(p * 8 + cc) * 16 + ol];
                dst[(hkv * SC_N + c0 + cc) * DIM + o] = a;
            }
        }
    }
}

// ---------------------------------------------------------------------------
// Merged NSA kernel (2 CTAs/SM, deferred denominator reduction).
// ---------------------------------------------------------------------------
__global__ void __launch_bounds__(256, 2) nsa_main(
    const float* __restrict__ q, const float* __restrict__ k,
    const float* __restrict__ v, const float* __restrict__ wg,
    float* __restrict__ out)
{
    __shared__ unsigned selmaskSh[QT];
    __shared__ int blkList[32];
    __shared__ int nblkSh;

    float* ckT = pool3;
    float* cvT = pool3 + 9728;
    float* qs  = pool3 + 19456;
    float* pkv = pool3 + 23808;

    const int bxr  = gridDim.x - 1 - blockIdx.x;   // heavy-first
    const int hkv  = bxr & 1;
    const int s0   = (bxr >> 1) * QT;
    const int tid  = threadIdx.x;
    const int lane = tid & 31;
    const int warp = tid >> 5;
    const int s    = s0 + warp;

    // ---- stage ck/cv tiles ----
    {
        const float* ckb = g_ck + hkv * SC_N * DIM;
        const float* cvb = g_cv + hkv * SC_N * DIM;
        for (int idx = tid; idx < 128 * 16; idx += NT) {
            int row = idx >> 4, quad = idx & 15;
            int c = row < SC_N ? row : SC_N - 1;
            cp16(ckT + row * RS + quad * 4, ckb + c * DIM + quad * 4);
            cp16(cvT + row * RS + quad * 4, cvb + c * DIM + quad * 4);
        }
        CP_COMMIT();
    }

    // ---- q fragments, gates, stage q ----
    float gate0, gate1, gate2;
    {
        const int h   = lane >> 2;
        const int d16 = lane & 3;
        const float4* qrow = (const float4*)(q + (s * HQ + hkv * GQA + h) * DIM);
        float4 qf[4];
        #pragma unroll
        for (int r = 0; r < 4; ++r) qf[r] = __ldg(&qrow[d16 * 4 + r]);
        #pragma unroll
        for (int e = 0; e < 3; ++e) {
            const float4* wrow = (const float4*)(wg + e * DIM);
            float a = 0.f;
            #pragma unroll
            for (int r = 0; r < 4; ++r) a += dot4(qf[r], __ldg(&wrow[d16 * 4 + r]));
            a += __shfl_xor_sync(~0u, a, 1);
            a += __shfl_xor_sync(~0u, a, 2);
            if (e == 0) gate0 = a; else if (e == 1) gate1 = a; else gate2 = a;
        }
        float4* qdst = (float4*)(qs + warp * 544 + h * 68);
        #pragma unroll
        for (int r = 0; r < 4; ++r) qdst[d16 * 4 + r] = qf[r];
    }

    const int Nc = (s >= 31) ? (((s - 31) >> 4) + 1) : 0;
    const ulonglong2* qq2 = (const ulonglong2*)(qs + warp * 544);

    CP_WAIT0();
    __syncthreads();

    // ======================= PHASE 1: compressed branch =====================
    float scA[4][8];
    #pragma unroll
    for (int t = 0; t < 2; ++t) {
        u64t s1[8], s2[8];
        #pragma unroll
        for (int hh = 0; hh < 8; ++hh) { s1[hh] = 0ull; s2[hh] = 0ull; }
        const ulonglong2* kA = (const ulonglong2*)ckT + (t * 64 + lane) * RS2;
        const ulonglong2* kB = kA + 32 * RS2;
        #pragma unroll
        for (int d4 = 0; d4 < 16; ++d4) {
            ulonglong2 a = kA[d4];
            ulonglong2 bb = kB[d4];
            #pragma unroll
            for (int hh = 0; hh < 8; ++hh) {
                ulonglong2 qv = qq2[hh * 17 + d4];
                ffma2(s1[hh], qv.x, a.x);
                ffma2(s1[hh], qv.y, a.y);
                ffma2(s2[hh], qv.x, bb.x);
                ffma2(s2[hh], qv.y, bb.y);
            }
        }
        #pragma unroll
        for (int hh = 0; hh < 8; ++hh) {
            float2 f1 = unpack2(s1[hh]);
            float2 f2 = unpack2(s2[hh]);
            scA[2 * t][hh]     = (f1.x + f1.y) * SCALE;
            scA[2 * t + 1][hh] = (f2.x + f2.y) * SCALE;
        }
    }
    __syncthreads();    // ckT consumed; probs may overlay it

    {
        float* probsW = pool3 + warp * 1024;   // [128][8] overlay on ckT
        float* pkvW   = pkv + warp * 128;

        bool valid[4];
        #pragma unroll
        for (int ki = 0; ki < 4; ++ki) valid[ki] = (ki * 32 + lane) < Nc;

        // per-head exact max, then exp IN PLACE over scA
        #pragma unroll
        for (int hh = 0; hh < 8; ++hh) {
            float lm = -1e30f;
            #pragma unroll
            for (int ki = 0; ki < 4; ++ki)
                if (valid[ki]) lm = fmaxf(lm, scA[ki][hh]);
            #pragma unroll
            for (int off = 16; off; off >>= 1)
                lm = fmaxf(lm, __shfl_xor_sync(~0u, lm, off));
            #pragma unroll
            for (int ki = 0; ki < 4; ++ki)
                scA[ki][hh] = valid[ki] ? expf(scA[ki][hh] - lm) : 0.f;
        }

        float inv[8];
        #pragma unroll
        for (int hp = 0; hp < 4; ++hp) {
            float sa = scA[0][2*hp]   + scA[1][2*hp]   + scA[2][2*hp]   + scA[3][2*hp];
            float sb = scA[0][2*hp+1] + scA[1][2*hp+1] + scA[2][2*hp+1] + scA[3][2*hp+1];
            u64t p = pack2(sa, sb);
            #pragma unroll
            for (int off = 16; off; off >>= 1) {
                u64t o = __shfl_xor_sync(~0u, p, off);
                add2(p, p, o);
            }
            float2 f = unpack2(p);
            inv[2*hp]   = (f.x > 0.f) ? (1.f / f.x) : 0.f;
            inv[2*hp+1] = (f.y > 0.f) ? (1.f / f.y) : 0.f;
        }

        #pragma unroll
        for (int ki = 0; ki < 4; ++ki) {
            int c = ki * 32 + lane;
            float p0 = scA[ki][0]*inv[0], p1 = scA[ki][1]*inv[1];
            float p2 = scA[ki][2]*inv[2], p3 = scA[ki][3]*inv[3];
            float p4 = scA[ki][4]*inv[4], p5 = scA[ki][5]*inv[5];
            float p6 = scA[ki][6]*inv[6], p7 = scA[ki][7]*inv[7];
            float4* pw = (float4*)(probsW + c * 8);
            pw[0] = make_float4(p0, p1, p2, p3);
            pw[1] = make_float4(p4, p5, p6, p7);
            pkvW[c] = p0 + p1 + p2 + p3 + p4 + p5 + p6 + p7;
        }
        __syncwarp();

        // pooling + top-8
        {
            float myval;
            if (lane < NOUT) {
                const float* pv = pkvW + lane * 4;
                myval = (pv[0] + pv[1] + pv[2] + pv[3] + pv[4]) / 5.0f;
            } else {
                myval = -1.0f;
            }
            if (lane == (s >> 6)) myval = __int_as_float(0x7f800000);
            unsigned mask = 0;
            #pragma unroll
            for (int r = 0; r < KSEL; ++r) {
                float bv = myval; int bi = lane;
                #pragma unroll
                for (int off = 16; off; off >>= 1) {
                    float ov = __shfl_xor_sync(~0u, bv, off);
                    int   oi = __shfl_xor_sync(~0u, bi, off);
                    if (ov > bv || (ov == bv && oi < bi)) { bv = ov; bi = oi; }
                }
                mask |= 1u << bi;
                if (lane == bi) myval = __int_as_float(0xff800000);
            }
            if (lane == 0) selmaskSh[warp] = mask;
        }

        // cmp PV -> out = g2 * cmp
        u64t acc2[8];
        #pragma unroll
        for (int i = 0; i < 8; ++i) acc2[i] = 0ull;
        const u64t* vB = (const u64t*)cvT + lane;
        const float4* pB = (const float4*)probsW;
        #pragma unroll 2
        for (int c = 0; c < Nc; ++c) {
            u64t vj = vB[c * RSU];
            float4 pa = pB[c * 2], pb = pB[c * 2 + 1];
            ffma2(acc2[0], pack2(pa.x, pa.x), vj);
            ffma2(acc2[1], pack2(pa.y, pa.y), vj);
            ffma2(acc2[2], pack2(pa.z, pa.z), vj);
            ffma2(acc2[3], pack2(pa.w, pa.w), vj);
            ffma2(acc2[4], pack2(pb.x, pb.x), vj);
            ffma2(acc2[5], pack2(pb.y, pb.y), vj);
            ffma2(acc2[6], pack2(pb.z, pb.z), vj);
            ffma2(acc2[7], pack2(pb.w, pb.w), vj);
        }
        #pragma unroll
        for (int hh = 0; hh < 8; ++hh) {
            float g2h = __shfl_sync(~0u, gate2, hh * 4);
            float2 a = unpack2(acc2[hh]);
            float2* op = (float2*)(out + (s * HQ + hkv * GQA + hh) * DIM + 2 * lane);
            *op = make_float2(g2h * a.x, g2h * a.y);
        }
    }

    // ======================= PHASE 2: sel + swa ==============================
    __syncthreads();
    if (tid == 0) {
        unsigned cmb = 0;
        #pragma unroll
        for (int qq = 0; qq < QT; ++qq) cmb |= selmaskSh[qq];
        int loS = s0 - (WIN - 1); if (loS < 0) loS = 0;
        int lowBlk = loS >> 6;
        int hiBlk  = (s0 + QT - 1) >> 6;
        unsigned wmask = (hiBlk >= 31 ? 0xFFFFFFFFu : ((1u << (hiBlk + 1)) - 1u))
                       & ~((1u << lowBlk) - 1u);
        unsigned m = cmb | wmask;
        int n = 0;
        while (m) { int bb = __ffs(m) - 1; m &= m - 1; blkList[n++] = bb; }
        nblkSh = n;
    }
    __syncthreads();

    const unsigned selMine = selmaskSh[warp];
    const int nblk = nblkSh;

    u64t accS2[8], accW2[8], lsw2[8];     // lsw2 = PER-LANE partial sums now
    #pragma unroll
    for (int i = 0; i < 8; ++i) { accS2[i] = 0ull; accW2[i] = 0ull; lsw2[i] = 0ull; }
    float mU = -1e30f;
    const int winLo = s - (WIN - 1);
    float* probsW2 = pool3 + 23808 + warp * 512;

    {
        int base = blkList[0] * LB;
        float* Kd = pool3;
        float* Vd = pool3 + 4864;
        #pragma unroll
        for (int r = 0; r < 4; ++r) {
            int idx = tid + r * NT;
            int row = idx >> 4, quad = idx & 15;
            int pos = base + row;
            cp16(Kd + row * RS + quad * 4, (const float4*)(k + (pos * HKV + hkv) * DIM) + quad);
            cp16(Vd + row * RS + quad * 4, (const float4*)(v + (pos * HKV + hkv) * DIM) + quad);
        }
        CP_COMMIT();
    }

    for (int it = 0; it < nblk; ++it) {
        CP_WAIT0();
        __syncthreads();
        if (it + 1 < nblk) {
            int base = blkList[it + 1] * LB;
            float* Kd = pool3 + ((it + 1) & 1) * 9728;
            float* Vd = Kd + 4864;
            #pragma unroll
            for (int r = 0; r < 4; ++r) {
                int idx = tid + r * NT;
                int row = idx >> 4, quad = idx & 15;
                int pos = base + row;
                cp16(Kd + row * RS + quad * 4, (const float4*)(k + (pos * HKV + hkv) * DIM) + quad);
                cp16(Vd + row * RS + quad * 4, (const float4*)(v + (pos * HKV + hkv) * DIM) + quad);
            }
            CP_COMMIT();
        }
        const float* Kt = pool3 + (it & 1) * 9728;
        const float* Vt = Kt + 4864;
        const int b = blkList[it];
        const int base = b * LB;

        if (base > s) continue;
        const bool selAct = (selMine >> b) & 1u;
        const bool swaAct = (base + 63) >= winLo;
        if (!(selAct || swaAct)) continue;

        // ---- score pass ----
        u64t s1[8], s2[8];
        #pragma unroll
        for (int hh = 0; hh < 8; ++hh) { s1[hh] = 0ull; s2[hh] = 0ull; }
        {
            const ulonglong2* kA = (const ulonglong2*)Kt + lane * RS2;
            const ulonglong2* kB = kA + 32 * RS2;
            #pragma unroll
            for (int d4 = 0; d4 < 16; ++d4) {
                ulonglong2 a = kA[d4];
                ulonglong2 bb = kB[d4];
                #pragma unroll
                for (int hh = 0; hh < 8; ++hh) {
                    ulonglong2 qv = qq2[hh * 17 + d4];
                    ffma2(s1[hh], qv.x, a.x);
                    ffma2(s1[hh], qv.y, a.y);
                    ffma2(s2[hh], qv.x, bb.x);
                    ffma2(s2[hh], qv.y, bb.y);
                }
            }
        }

        const int jhi  = min(63, s - base);
        const int pos1 = base + lane;
        const bool c1 = (lane <= jhi);
        const bool c2 = (lane + 32 <= jhi);
        const bool w1 = c1 && (pos1 >= winLo);
        const bool w2 = c2 && (pos1 + 32 >= winLo);

        float sc1[8], sc2[8];
        float tS = -1e30f, tW = -1e30f;
        #pragma unroll
        for (int hh = 0; hh < 8; ++hh) {
            float2 f1 = unpack2(s1[hh]);
            float2 f2 = unpack2(s2[hh]);
            sc1[hh] = (f1.x + f1.y) * SCALE;
            sc2[hh] = (f2.x + f2.y) * SCALE;
            if (c1) { tS = fmaxf(tS, sc1[hh]); if (w1) tW = fmaxf(tW, sc1[hh]); }
            if (c2) { tS = fmaxf(tS, sc2[hh]); if (w2) tW = fmaxf(tW, sc2[hh]); }
        }
        #pragma unroll
        for (int off = 16; off; off >>= 1) {
            tS = fmaxf(tS, __shfl_xor_sync(~0u, tS, off));
            tW = fmaxf(tW, __shfl_xor_sync(~0u, tW, off));
        }

        const bool doS = selAct;
        const bool doW = swaAct && (tW > -1e29f);
        float t = -1e30f;
        if (doS) t = tS;
        if (doW) t = fmaxf(t, tW);
        if (t > mU) {
            float f = __expf(mU - t);
            u64t f2p = pack2(f, f);
            #pragma unroll
            for (int i = 0; i < 8; ++i) {
                mul2(accS2[i], accS2[i], f2p);
                mul2(accW2[i], accW2[i], f2p);
                mul2(lsw2[i], lsw2[i], f2p);
            }
            mU = t;
        }

        // exps IN PLACE over sc1/sc2
        #pragma unroll
        for (int hh = 0; hh < 8; ++hh) {
            sc1[hh] = __expf(sc1[hh] - mU);
            sc2[hh] = __expf(sc2[hh] - mU);
        }
        {
            float4* pw = (float4*)probsW2;
            if (c1) {
                pw[lane * 2]     = make_float4(sc1[0], sc1[1], sc1[2], sc1[3]);
                pw[lane * 2 + 1] = make_float4(sc1[4], sc1[5], sc1[6], sc1[7]);
            }
            if (c2) {
                pw[(lane + 32) * 2]     = make_float4(sc2[0], sc2[1], sc2[2], sc2[3]);
                pw[(lane + 32) * 2 + 1] = make_float4(sc2[4], sc2[5], sc2[6], sc2[7]);
            }
        }
        // PER-LANE partial masked sums (no per-tile butterfly!)
        #pragma unroll
        for (int hh = 0; hh < 8; ++hh) {
            float sS = (doS && c1 ? sc1[hh] : 0.f) + (doS && c2 ? sc2[hh] : 0.f);
            float sW = (w1 ? sc1[hh] : 0.f) + (w2 ? sc2[hh] : 0.f);
            add2(lsw2[hh], lsw2[hh], pack2(sS, sW));
        }
        __syncwarp();

        // ---- PV pass ----
        const u64t* vB = (const u64t*)Vt + lane;
        const float4* pB = (const float4*)probsW2;
        const int jlo = max(0, winLo - base);

        if (doS && doW) {
            for (int j = 0; j < jlo; ++j) {
                u64t vj = vB[j * RSU];
                float4 pa = pB[j * 2], pb = pB[j * 2 + 1];
                ffma2(accS2[0], pack2(pa.x, pa.x), vj);
                ffma2(accS2[1], pack2(pa.y, pa.y), vj);
                ffma2(accS2[2], pack2(pa.z, pa.z), vj);
                ffma2(accS2[3], pack2(pa.w, pa.w), vj);
                ffma2(accS2[4], pack2(pb.x, pb.x), vj);
                ffma2(accS2[5], pack2(pb.y, pb.y), vj);
                ffma2(accS2[6], pack2(pb.z, pb.z), vj);
                ffma2(accS2[7], pack2(pb.w, pb.w), vj);
            }
            u64t accT2[8];
            #pragma unroll
            for (int i = 0; i < 8; ++i) accT2[i] = 0ull;
            for (int j = jlo; j <= jhi; ++j) {
                u64t vj = vB[j * RSU];
                float4 pa = pB[j * 2], pb = pB[j * 2 + 1];
                ffma2(accT2[0], pack2(pa.x, pa.x), vj);
                ffma2(accT2[1], pack2(pa.y, pa.y), vj);
                ffma2(accT2[2], pack2(pa.z, pa.z), vj);
                ffma2(accT2[3], pack2(pa.w, pa.w), vj);
                ffma2(accT2[4], pack2(pb.x, pb.x), vj);
                ffma2(accT2[5], pack2(pb.y, pb.y), vj);
                ffma2(accT2[6], pack2(pb.z, pb.z), vj);
                ffma2(accT2[7], pack2(pb.w, pb.w), vj);
            }
            #pragma unroll
            for (int i = 0; i < 8; ++i) {
                add2(accS2[i], accS2[i], accT2[i]);
                add2(accW2[i], accW2[i], accT2[i]);
            }
        } else if (doS) {
            for (int j = 0; j <= jhi; ++j) {
                u64t vj = vB[j * RSU];
                float4 pa = pB[j * 2], pb = pB[j * 2 + 1];
                ffma2(accS2[0], pack2(pa.x, pa.x), vj);
                ffma2(accS2[1], pack2(pa.y, pa.y), vj);
                ffma2(accS2[2], pack2(pa.z, pa.z), vj);
                ffma2(accS2[3], pack2(pa.w, pa.w), vj);
                ffma2(accS2[4], pack2(pb.x, pb.x), vj);
                ffma2(accS2[5], pack2(pb.y, pb.y), vj);
                ffma2(accS2[6], pack2(pb.z, pb.z), vj);
                ffma2(accS2[7], pack2(pb.w, pb.w), vj);
            }
        } else if (doW) {
            for (int j = jlo; j <= jhi; ++j) {
                u64t vj = vB[j * RSU];
                float4 pa = pB[j * 2], pb = pB[j * 2 + 1];
                ffma2(accW2[0], pack2(pa.x, pa.x), vj);
                ffma2(accW2[1], pack2(pa.y, pa.y), vj);
                ffma2(accW2[2], pack2(pa.z, pa.z), vj);
                ffma2(accW2[3], pack2(pa.w, pa.w), vj);
                ffma2(accW2[4], pack2(pb.x, pb.x), vj);
                ffma2(accW2[5], pack2(pb.y, pb.y), vj);
                ffma2(accW2[6], pack2(pb.z, pb.z), vj);
                ffma2(accW2[7], pack2(pb.w, pb.w), vj);
            }
        }
    }

    // ---- final denominator reduction (once) ----
    #pragma unroll
    for (int off = 16; off; off >>= 1) {
        #pragma unroll
        for (int hh = 0; hh < 8; ++hh) {
            u64t o = __shfl_xor_sync(~0u, lsw2[hh], off);
            add2(lsw2[hh], lsw2[hh], o);
        }
    }

    // ---- combine per head, RMW of phase-1 result ----
    #pragma unroll
    for (int hh = 0; hh < 8; ++hh) {
        float g0 = __shfl_sync(~0u, gate0, hh * 4);
        float g1 = __shfl_sync(~0u, gate1, hh * 4);
        float2 lw = unpack2(lsw2[hh]);
        float invS = g0 / fmaxf(lw.x, 1e-20f);
        float invW = g1 / fmaxf(lw.y, 1e-20f);
        float2 aS = unpack2(accS2[hh]);
        float2 aW = unpack2(accW2[hh]);
        float2* op = (float2*)(out + (s * HQ + hkv * GQA + hh) * DIM + 2 * lane);
        float2 cur = *op;
        cur.x += invS * aS.x + invW * aW.x;
        cur.y += invS * aS.y + invW * aW.y;
        *op = cur;
    }
}

// ---------------------------------------------------------------------------
extern "C" void kernel_launch(void* const* d_in, const int* in_sizes, int n_in,
                              void* d_out, int out_size)
{
    const float* q  = (const float*)d_in[0];
    const float* k  = (const float*)d_in[1];
    const float* v  = (const float*)d_in[2];
    const float* wk = (const float*)d_in[3];
    const float* wv = (const float*)d_in[4];
    const float* wg = (const float*)d_in[5];
    float* out = (float*)d_out;

    compress_kernel<<<256, NT>>>(k, v, wk, wv);

    const size_t smem_bytes = 27904 * sizeof(float);   // 111616 B
    cudaFuncSetAttribute(nsa_main,
                         cudaFuncAttributeMaxDynamicSharedMemorySize, (int)smem_bytes);
    nsa_main<<<(S_LEN / QT) * HKV, NT, smem_bytes>>>(q, k, v, wg, out);
}

// round 13
// speedup vs baseline: 1.0630x; 1.0213x over previous
#include <cuda_runtime.h>
#include <cstdint>

#define S_LEN  2048
#define HKV    2
#define HQ     16
#define GQA    8
#define DIM    64
#define LC     32
#define CSTRIDE 16
#define LB     64
#define KSEL   8
#define WIN    512
#define SC_N   127
#define NOUT   31
#define SCALE  0.125f
#define QT     8
#define NT     256
#define RS     76            // padded row stride (floats): conflict-free LDS.128
#define RS2    19            // RS in ulonglong2
#define RSU    38            // RS in u64

typedef unsigned long long u64t;

__device__ float g_ck[HKV * SC_N * DIM];
__device__ float g_cv[HKV * SC_N * DIM];

__device__ __forceinline__ float dot4(float4 a, float4 b) {
    return a.x * b.x + a.y * b.y + a.z * b.z + a.w * b.w;
}
__device__ __forceinline__ void ffma2(u64t& d, u64t a, u64t b) {
    asm("fma.rn.f32x2 %0, %1, %2, %0;" : "+l"(d) : "l"(a), "l"(b));
}
__device__ __forceinline__ void add2(u64t& d, u64t a, u64t b) {
    asm("add.rn.f32x2 %0, %1, %2;" : "=l"(d) : "l"(a), "l"(b));
}
__device__ __forceinline__ u64t pack2(float lo, float hi) {
    u64t r; asm("mov.b64 %0, {%1, %2};" : "=l"(r) : "f"(lo), "f"(hi)); return r;
}
__device__ __forceinline__ float2 unpack2(u64t a) {
    float2 r; asm("mov.b64 {%0, %1}, %2;" : "=f"(r.x), "=f"(r.y) : "l"(a)); return r;
}
__device__ __forceinline__ void cp16(void* sdst, const void* gsrc) {
    uint32_t sa = (uint32_t)__cvta_generic_to_shared(sdst);
    asm volatile("cp.async.cg.shared.global [%0], [%1], 16;" :: "r"(sa), "l"(gsrc));
}
#define CP_COMMIT() asm volatile("cp.async.commit_group;")
#define CP_WAIT0()  asm volatile("cp.async.wait_group 0;")

extern __shared__ float pool3[];

// ---------------------------------------------------------------------------
// conv1d compressor: block = (hkv, k/v, o-quarter, 8 compressed positions)
// ---------------------------------------------------------------------------
__global__ void __launch_bounds__(256) compress_kernel(
    const float* __restrict__ k, const float* __restrict__ v,
    const float* __restrict__ wk, const float* __restrict__ wv)
{
    const int b     = blockIdx.x;        // 256 blocks
    const int hkv   = b & 1;
    const int isV   = (b >> 1) & 1;
    const int oq    = (b >> 2) & 3;
    const int c0    = (b >> 4) * 8;
    const float* src = isV ? v : k;
    const float* w   = isV ? wv : wk;
    float* dst = isV ? g_cv : g_ck;

    __shared__ float xs[144 * 64];
    __shared__ float red[16 * 8 * 16];
    const int tid = threadIdx.x;

    for (int idx = tid; idx < 144 * 16; idx += NT) {
        int row = idx >> 4, quad = idx & 15;
        int pos = c0 * CSTRIDE + row;
        float4 val = make_float4(0.f, 0.f, 0.f, 0.f);
        if (pos < S_LEN)
            val = __ldg((const float4*)(src + (pos * HKV + hkv) * DIM) + quad);
        ((float4*)(xs + row * 64))[quad] = val;
    }
    __syncthreads();

    const int ol   = tid & 15;
    const int o    = oq * 16 + ol;
    const int part = tid >> 4;
    float acc[8];
    #pragma unroll
    for (int cc = 0; cc < 8; ++cc) acc[cc] = 0.f;

    for (int i = part * 4; i < part * 4 + 4; ++i) {
        const float4* w4 = (const float4*)(w + (o * DIM + i) * LC);
        #pragma unroll
        for (int t4 = 0; t4 < 8; ++t4) {
            float4 a = __ldg(&w4[t4]);
            int t = t4 * 4;
            #pragma unroll
            for (int cc = 0; cc < 8; ++cc) {
                const float* xr = xs + (cc * 16 + t) * 64 + i;
                acc[cc] += a.x * xr[0] + a.y * xr[64] + a.z * xr[128] + a.w * xr[192];
            }
        }
    }
    #pragma unroll
    for (int cc = 0; cc < 8; ++cc) red[(part * 8 + cc) * 16 + ol] = acc[cc];
    __syncthreads();
    if (part == 0) {
        #pragma unroll
        for (int cc = 0; cc < 8; ++cc) {
            if (c0 + cc < SC_N) {
                float a = 0.f;
                #pragma unroll
                for (int p = 0; p < 16; ++p) a += red[(p * 8 + cc) * 16 + ol];
                dst[(hkv * SC_N + c0 + cc) * DIM + o] = a;
            }
        }
    }
}

// ---------------------------------------------------------------------------
// Merged NSA kernel. Phase 2 uses direct exp (no online max).
// ---------------------------------------------------------------------------
__global__ void __launch_bounds__(256, 2) nsa_main(
    const float* __restrict__ q, const float* __restrict__ k,
    const float* __restrict__ v, const float* __restrict__ wg,
    float* __restrict__ out)
{
    __shared__ unsigned selmaskSh[QT];
    __shared__ int blkList[32];
    __shared__ int nblkSh;

    float* ckT = pool3;
    float* cvT = pool3 + 9728;
    float* qs  = pool3 + 19456;
    float* pkv = pool3 + 23808;

    const int bxr  = gridDim.x - 1 - blockIdx.x;   // heavy-first
    const int hkv  = bxr & 1;
    const int s0   = (bxr >> 1) * QT;
    const int tid  = threadIdx.x;
    const int lane = tid & 31;
    const int warp = tid >> 5;
    const int s    = s0 + warp;

    // ---- stage ck/cv tiles ----
    {
        const float* ckb = g_ck + hkv * SC_N * DIM;
        const float* cvb = g_cv + hkv * SC_N * DIM;
        for (int idx = tid; idx < 128 * 16; idx += NT) {
            int row = idx >> 4, quad = idx & 15;
            int c = row < SC_N ? row : SC_N - 1;
            cp16(ckT + row * RS + quad * 4, ckb + c * DIM + quad * 4);
            cp16(cvT + row * RS + quad * 4, cvb + c * DIM + quad * 4);
        }
        CP_COMMIT();
    }

    // ---- q fragments, gates, stage q ----
    float gate0, gate1, gate2;
    {
        const int h   = lane >> 2;
        const int d16 = lane & 3;
        const float4* qrow = (const float4*)(q + (s * HQ + hkv * GQA + h) * DIM);
        float4 qf[4];
        #pragma unroll
        for (int r = 0; r < 4; ++r) qf[r] = __ldg(&qrow[d16 * 4 + r]);
        #pragma unroll
        for (int e = 0; e < 3; ++e) {
            const float4* wrow = (const float4*)(wg + e * DIM);
            float a = 0.f;
            #pragma unroll
            for (int r = 0; r < 4; ++r) a += dot4(qf[r], __ldg(&wrow[d16 * 4 + r]));
            a += __shfl_xor_sync(~0u, a, 1);
            a += __shfl_xor_sync(~0u, a, 2);
            if (e == 0) gate0 = a; else if (e == 1) gate1 = a; else gate2 = a;
        }
        float4* qdst = (float4*)(qs + warp * 544 + h * 68);
        #pragma unroll
        for (int r = 0; r < 4; ++r) qdst[d16 * 4 + r] = qf[r];
    }

    const int Nc = (s >= 31) ? (((s - 31) >> 4) + 1) : 0;
    const ulonglong2* qq2 = (const ulonglong2*)(qs + warp * 544);

    CP_WAIT0();
    __syncthreads();

    // ======================= PHASE 1: compressed branch =====================
    float scA[4][8];
    #pragma unroll
    for (int t = 0; t < 2; ++t) {
        u64t s1[8], s2[8];
        #pragma unroll
        for (int hh = 0; hh < 8; ++hh) { s1[hh] = 0ull; s2[hh] = 0ull; }
        const ulonglong2* kA = (const ulonglong2*)ckT + (t * 64 + lane) * RS2;
        const ulonglong2* kB = kA + 32 * RS2;
        #pragma unroll
        for (int d4 = 0; d4 < 16; ++d4) {
            ulonglong2 a = kA[d4];
            ulonglong2 bb = kB[d4];
            #pragma unroll
            for (int hh = 0; hh < 8; ++hh) {
                ulonglong2 qv = qq2[hh * 17 + d4];
                ffma2(s1[hh], qv.x, a.x);
                ffma2(s1[hh], qv.y, a.y);
                ffma2(s2[hh], qv.x, bb.x);
                ffma2(s2[hh], qv.y, bb.y);
            }
        }
        #pragma unroll
        for (int hh = 0; hh < 8; ++hh) {
            float2 f1 = unpack2(s1[hh]);
            float2 f2 = unpack2(s2[hh]);
            scA[2 * t][hh]     = (f1.x + f1.y) * SCALE;
            scA[2 * t + 1][hh] = (f2.x + f2.y) * SCALE;
        }
    }
    __syncthreads();    // ckT consumed; probs may overlay it

    {
        float* probsW = pool3 + warp * 1024;   // [128][8] overlay on ckT
        float* pkvW   = pkv + warp * 128;

        bool valid[4];
        #pragma unroll
        for (int ki = 0; ki < 4; ++ki) valid[ki] = (ki * 32 + lane) < Nc;

        // per-head exact max, exp IN PLACE (keeps top-k selection bit-stable)
        #pragma unroll
        for (int hh = 0; hh < 8; ++hh) {
            float lm = -1e30f;
            #pragma unroll
            for (int ki = 0; ki < 4; ++ki)
                if (valid[ki]) lm = fmaxf(lm, scA[ki][hh]);
            #pragma unroll
            for (int off = 16; off; off >>= 1)
                lm = fmaxf(lm, __shfl_xor_sync(~0u, lm, off));
            #pragma unroll
            for (int ki = 0; ki < 4; ++ki)
                scA[ki][hh] = valid[ki] ? expf(scA[ki][hh] - lm) : 0.f;
        }

        float inv[8];
        #pragma unroll
        for (int hp = 0; hp < 4; ++hp) {
            float sa = scA[0][2*hp]   + scA[1][2*hp]   + scA[2][2*hp]   + scA[3][2*hp];
            float sb = scA[0][2*hp+1] + scA[1][2*hp+1] + scA[2][2*hp+1] + scA[3][2*hp+1];
            u64t p = pack2(sa, sb);
            #pragma unroll
            for (int off = 16; off; off >>= 1) {
                u64t o = __shfl_xor_sync(~0u, p, off);
                add2(p, p, o);
            }
            float2 f = unpack2(p);
            inv[2*hp]   = (f.x > 0.f) ? (1.f / f.x) : 0.f;
            inv[2*hp+1] = (f.y > 0.f) ? (1.f / f.y) : 0.f;
        }

        #pragma unroll
        for (int ki = 0; ki < 4; ++ki) {
            int c = ki * 32 + lane;
            float p0 = scA[ki][0]*inv[0], p1 = scA[ki][1]*inv[1];
            float p2 = scA[ki][2]*inv[2], p3 = scA[ki][3]*inv[3];
            float p4 = scA[ki][4]*inv[4], p5 = scA[ki][5]*inv[5];
            float p6 = scA[ki][6]*inv[6], p7 = scA[ki][7]*inv[7];
            float4* pw = (float4*)(probsW + c * 8);
            pw[0] = make_float4(p0, p1, p2, p3);
            pw[1] = make_float4(p4, p5, p6, p7);
            pkvW[c] = p0 + p1 + p2 + p3 + p4 + p5 + p6 + p7;
        }
        __syncwarp();

        // pooling + top-8
        {
            float myval;
            if (lane < NOUT) {
                const float* pv = pkvW + lane * 4;
                myval = (pv[0] + pv[1] + pv[2] + pv[3] + pv[4]) / 5.0f;
            } else {
                myval = -1.0f;
            }
            if (lane == (s >> 6)) myval = __int_as_float(0x7f800000);
            unsigned mask = 0;
            #pragma unroll
            for (int r = 0; r < KSEL; ++r) {
                float bv = myval; int bi = lane;
                #pragma unroll
                for (int off = 16; off; off >>= 1) {
                    float ov = __shfl_xor_sync(~0u, bv, off);
                    int   oi = __shfl_xor_sync(~0u, bi, off);
                    if (ov > bv || (ov == bv && oi < bi)) { bv = ov; bi = oi; }
                }
                mask |= 1u << bi;
                if (lane == bi) myval = __int_as_float(0xff800000);
            }
            if (lane == 0) selmaskSh[warp] = mask;
        }

        // cmp PV -> out = g2 * cmp
        u64t acc2[8];
        #pragma unroll
        for (int i = 0; i < 8; ++i) acc2[i] = 0ull;
        const u64t* vB = (const u64t*)cvT + lane;
        const float4* pB = (const float4*)probsW;
        #pragma unroll 2
        for (int c = 0; c < Nc; ++c) {
            u64t vj = vB[c * RSU];
            float4 pa = pB[c * 2], pb = pB[c * 2 + 1];
            ffma2(acc2[0], pack2(pa.x, pa.x), vj);
            ffma2(acc2[1], pack2(pa.y, pa.y), vj);
            ffma2(acc2[2], pack2(pa.z, pa.z), vj);
            ffma2(acc2[3], pack2(pa.w, pa.w), vj);
            ffma2(acc2[4], pack2(pb.x, pb.x), vj);
            ffma2(acc2[5], pack2(pb.y, pb.y), vj);
            ffma2(acc2[6], pack2(pb.z, pb.z), vj);
            ffma2(acc2[7], pack2(pb.w, pb.w), vj);
        }
        #pragma unroll
        for (int hh = 0; hh < 8; ++hh) {
            float g2h = __shfl_sync(~0u, gate2, hh * 4);
            float2 a = unpack2(acc2[hh]);
            float2* op = (float2*)(out + (s * HQ + hkv * GQA + hh) * DIM + 2 * lane);
            *op = make_float2(g2h * a.x, g2h * a.y);
        }
    }

    // ======================= PHASE 2: sel + swa (direct exp) ================
    __syncthreads();
    if (tid == 0) {
        unsigned cmb = 0;
        #pragma unroll
        for (int qq = 0; qq < QT; ++qq) cmb |= selmaskSh[qq];
        int loS = s0 - (WIN - 1); if (loS < 0) loS = 0;
        int lowBlk = loS >> 6;
        int hiBlk  = (s0 + QT - 1) >> 6;
        unsigned wmask = (hiBlk >= 31 ? 0xFFFFFFFFu : ((1u << (hiBlk + 1)) - 1u))
                       & ~((1u << lowBlk) - 1u);
        unsigned m = cmb | wmask;
        int n = 0;
        while (m) { int bb = __ffs(m) - 1; m &= m - 1; blkList[n++] = bb; }
        nblkSh = n;
    }
    __syncthreads();

    const unsigned selMine = selmaskSh[warp];
    const int nblk = nblkSh;

    u64t accS2[8], accW2[8], lsw2[8];     // lsw2 = per-lane partial (sel,win) sums
    #pragma unroll
    for (int i = 0; i < 8; ++i) { accS2[i] = 0ull; accW2[i] = 0ull; lsw2[i] = 0ull; }
    const int winLo = s - (WIN - 1);
    float* probsW2 = pool3 + 23808 + warp * 512;

    {
        int base = blkList[0] * LB;
        float* Kd = pool3;
        float* Vd = pool3 + 4864;
        #pragma unroll
        for (int r = 0; r < 4; ++r) {
            int idx = tid + r * NT;
            int row = idx >> 4, quad = idx & 15;
            int pos = base + row;
            cp16(Kd + row * RS + quad * 4, (const float4*)(k + (pos * HKV + hkv) * DIM) + quad);
            cp16(Vd + row * RS + quad * 4, (const float4*)(v + (pos * HKV + hkv) * DIM) + quad);
        }
        CP_COMMIT();
    }

    for (int it = 0; it < nblk; ++it) {
        CP_WAIT0();
        __syncthreads();
        if (it + 1 < nblk) {
            int base = blkList[it + 1] * LB;
            float* Kd = pool3 + ((it + 1) & 1) * 9728;
            float* Vd = Kd + 4864;
            #pragma unroll
            for (int r = 0; r < 4; ++r) {
                int idx = tid + r * NT;
                int row = idx >> 4, quad = idx & 15;
                int pos = base + row;
                cp16(Kd + row * RS + quad * 4, (const float4*)(k + (pos * HKV + hkv) * DIM) + quad);
                cp16(Vd + row * RS + quad * 4, (const float4*)(v + (pos * HKV + hkv) * DIM) + quad);
            }
            CP_COMMIT();
        }
        const float* Kt = pool3 + (it & 1) * 9728;
        const float* Vt = Kt + 4864;
        const int b = blkList[it];
        const int base = b * LB;

        if (base > s) continue;
        const int jhi = min(63, s - base);
        const int jlo = max(0, winLo - base);
        const bool doS = (selMine >> b) & 1u;
        const bool doW = (jlo <= jhi);
        if (!(doS || doW)) continue;

        // ---- score pass ----
        u64t s1[8], s2[8];
        #pragma unroll
        for (int hh = 0; hh < 8; ++hh) { s1[hh] = 0ull; s2[hh] = 0ull; }
        {
            const ulonglong2* kA = (const ulonglong2*)Kt + lane * RS2;
            const ulonglong2* kB = kA + 32 * RS2;
            #pragma unroll
            for (int d4 = 0; d4 < 16; ++d4) {
                ulonglong2 a = kA[d4];
                ulonglong2 bb = kB[d4];
                #pragma unroll
                for (int hh = 0; hh < 8; ++hh) {
                    ulonglong2 qv = qq2[hh * 17 + d4];
                    ffma2(s1[hh], qv.x, a.x);
                    ffma2(s1[hh], qv.y, a.y);
                    ffma2(s2[hh], qv.x, bb.x);
                    ffma2(s2[hh], qv.y, bb.y);
                }
            }
        }

        const int pos1 = base + lane;
        const bool c1 = (lane <= jhi);
        const bool c2 = (lane + 32 <= jhi);
        const bool w1 = c1 && (pos1 >= winLo);
        const bool w2 = c2 && (pos1 + 32 >= winLo);

        // direct exp (scores bounded; no max subtraction)
        float sc1[8], sc2[8];
        #pragma unroll
        for (int hh = 0; hh < 8; ++hh) {
            float2 f1 = unpack2(s1[hh]);
            float2 f2 = unpack2(s2[hh]);
            sc1[hh] = __expf((f1.x + f1.y) * SCALE);
            sc2[hh] = __expf((f2.x + f2.y) * SCALE);
        }
        {
            float4* pw = (float4*)probsW2;
            if (c1) {
                pw[lane * 2]     = make_float4(sc1[0], sc1[1], sc1[2], sc1[3]);
                pw[lane * 2 + 1] = make_float4(sc1[4], sc1[5], sc1[6], sc1[7]);
            }
            if (c2) {
                pw[(lane + 32) * 2]     = make_float4(sc2[0], sc2[1], sc2[2], sc2[3]);
                pw[(lane + 32) * 2 + 1] = make_float4(sc2[4], sc2[5], sc2[6], sc2[7]);
            }
        }
        // per-lane partial masked sums
        #pragma unroll
        for (int hh = 0; hh < 8; ++hh) {
            float sS = (doS && c1 ? sc1[hh] : 0.f) + (doS && c2 ? sc2[hh] : 0.f);
            float sW = (w1 ? sc1[hh] : 0.f) + (w2 ? sc2[hh] : 0.f);
            add2(lsw2[hh], lsw2[hh], pack2(sS, sW));
        }
        __syncwarp();

        // ---- PV pass ----
        const u64t* vB = (const u64t*)Vt + lane;
        const float4* pB = (const float4*)probsW2;

        if (doS && doW) {
            for (int j = 0; j < jlo; ++j) {
                u64t vj = vB[j * RSU];
                float4 pa = pB[j * 2], pb = pB[j * 2 + 1];
                ffma2(accS2[0], pack2(pa.x, pa.x), vj);
                ffma2(accS2[1], pack2(pa.y, pa.y), vj);
                ffma2(accS2[2], pack2(pa.z, pa.z), vj);
                ffma2(accS2[3], pack2(pa.w, pa.w), vj);
                ffma2(accS2[4], pack2(pb.x, pb.x), vj);
                ffma2(accS2[5], pack2(pb.y, pb.y), vj);
                ffma2(accS2[6], pack2(pb.z, pb.z), vj);
                ffma2(accS2[7], pack2(pb.w, pb.w), vj);
            }
            u64t accT2[8];
            #pragma unroll
            for (int i = 0; i < 8; ++i) accT2[i] = 0ull;
            for (int j = jlo; j <= jhi; ++j) {
                u64t vj = vB[j * RSU];
                float4 pa = pB[j * 2], pb = pB[j * 2 + 1];
                ffma2(accT2[0], pack2(pa.x, pa.x), vj);
                ffma2(accT2[1], pack2(pa.y, pa.y), vj);
                ffma2(accT2[2], pack2(pa.z, pa.z), vj);
                ffma2(accT2[3], pack2(pa.w, pa.w), vj);
                ffma2(accT2[4], pack2(pb.x, pb.x), vj);
                ffma2(accT2[5], pack2(pb.y, pb.y), vj);
                ffma2(accT2[6], pack2(pb.z, pb.z), vj);
                ffma2(accT2[7], pack2(pb.w, pb.w), vj);
            }
            #pragma unroll
            for (int i = 0; i < 8; ++i) {
                add2(accS2[i], accS2[i], accT2[i]);
                add2(accW2[i], accW2[i], accT2[i]);
            }
        } else if (doS) {
            for (int j = 0; j <= jhi; ++j) {
                u64t vj = vB[j * RSU];
                float4 pa = pB[j * 2], pb = pB[j * 2 + 1];
                ffma2(accS2[0], pack2(pa.x, pa.x), vj);
                ffma2(accS2[1], pack2(pa.y, pa.y), vj);
                ffma2(accS2[2], pack2(pa.z, pa.z), vj);
                ffma2(accS2[3], pack2(pa.w, pa.w), vj);
                ffma2(accS2[4], pack2(pb.x, pb.x), vj);
                ffma2(accS2[5], pack2(pb.y, pb.y), vj);
                ffma2(accS2[6], pack2(pb.z, pb.z), vj);
                ffma2(accS2[7], pack2(pb.w, pb.w), vj);
            }
        } else {
            for (int j = jlo; j <= jhi; ++j) {
                u64t vj = vB[j * RSU];
                float4 pa = pB[j * 2], pb = pB[j * 2 + 1];
                ffma2(accW2[0], pack2(pa.x, pa.x), vj);
                ffma2(accW2[1], pack2(pa.y, pa.y), vj);
                ffma2(accW2[2], pack2(pa.z, pa.z), vj);
                ffma2(accW2[3], pack2(pa.w, pa.w), vj);
                ffma2(accW2[4], pack2(pb.x, pb.x), vj);
                ffma2(accW2[5], pack2(pb.y, pb.y), vj);
                ffma2(accW2[6], pack2(pb.z, pb.z), vj);
                ffma2(accW2[7], pack2(pb.w, pb.w), vj);
            }
        }
    }

    // ---- final denominator reduction ----
    #pragma unroll
    for (int off = 16; off; off >>= 1) {
        #pragma unroll
        for (int hh = 0; hh < 8; ++hh) {
            u64t o = __shfl_xor_sync(~0u, lsw2[hh], off);
            add2(lsw2[hh], lsw2[hh], o);
        }
    }

    // ---- combine per head, RMW of phase-1 result ----
    #pragma unroll
    for (int hh = 0; hh < 8; ++hh) {
        float g0 = __shfl_sync(~0u, gate0, hh * 4);
        float g1 = __shfl_sync(~0u, gate1, hh * 4);
        float2 lw = unpack2(lsw2[hh]);
        float invS = g0 / fmaxf(lw.x, 1e-20f);
        float invW = g1 / fmaxf(lw.y, 1e-20f);
        float2 aS = unpack2(accS2[hh]);
        float2 aW = unpack2(accW2[hh]);
        float2* op = (float2*)(out + (s * HQ + hkv * GQA + hh) * DIM + 2 * lane);
        float2 cur = *op;
        cur.x += invS * aS.x + invW * aW.x;
        cur.y += invS * aS.y + invW * aW.y;
        *op = cur;
    }
}

// ---------------------------------------------------------------------------
extern "C" void kernel_launch(void* const* d_in, const int* in_sizes, int n_in,
                              void* d_out, int out_size)
{
    const float* q  = (const float*)d_in[0];
    const float* k  = (const float*)d_in[1];
    const float* v  = (const float*)d_in[2];
    const float* wk = (const float*)d_in[3];
    const float* wv = (const float*)d_in[4];
    const float* wg = (const float*)d_in[5];
    float* out = (float*)d_out;

    compress_kernel<<<256, NT>>>(k, v, wk, wv);

    const size_t smem_bytes = 27904 * sizeof(float);   // 111616 B
    cudaFuncSetAttribute(nsa_main,
                         cudaFuncAttributeMaxDynamicSharedMemorySize, (int)smem_bytes);
    nsa_main<<<(S_LEN / QT) * HKV, NT, smem_bytes>>>(q, k, v, wg, out);
}